// round 9
// baseline (speedup 1.0000x reference)
#include <cuda_runtime.h>

// VelocityLoss on GB300 — R8 dataflow with CH=8 (wave-tail reduction:
// 3840 blocks -> 6.5 waves vs 3.2, tail waste ~20%->~7%) and shortened
// FMA dependency chain (premultiplied mv*rv).

namespace {
constexpr int B_  = 512;
constexpr int S_  = 480;
constexpr int F_  = 149;
constexpr int VF_ = 5;
constexpr int CH  = 8;                    // rows per warp chunk
constexpr int CPB = S_ / CH;              // 60
constexpr int WPB = 8;                    // 256 threads
constexpr int NBLK = B_ * CPB / WPB;      // 3840
}

__device__ double g_acc[3] = {0.0, 0.0, 0.0};
__device__ unsigned int g_ticket = 0;

// lane -> joint, part groups shuffle-aligned:
// lanes 0-7 part0, 8-11 part1, 12-15 part2, 16-19 part3, 20-23 part4
__constant__ int c_j[24] = {
    8, 9, 10, 11, 12, 21, 22, 23,
    0, 1, 2, 3,
    4, 5, 6, 7,
    13, 14, 15, 16,
    17, 18, 19, 20
};
__constant__ float c_wl[24] = {
    1.f/9, 1.f/9, 1.f/9, 1.f/9, 1.f/9, 1.f/9, 2.f/9, 1.f/9,
    0.1f, 0.2f, 0.3f, 0.4f,
    0.1f, 0.2f, 0.3f, 0.4f,
    0.1f, 0.2f, 0.3f, 0.4f,
    0.1f, 0.2f, 0.3f, 0.4f
};

__global__ void __launch_bounds__(256, 4) vel_loss_ch8(
    const float* __restrict__ pred,   // (B, S, F)
    const float* __restrict__ tvft,   // (B, S+1, VF)
    const float* __restrict__ meanv,  // (F,)
    const float* __restrict__ stdv,   // (F,)
    float* __restrict__ out)
{
    const int tid  = threadIdx.x;
    const int lane = tid & 31;
    const int warp = tid >> 5;
    const int idx  = blockIdx.x * WPB + warp;
    const int b    = idx / CPB;
    const int s0   = (idx % CPB) * CH;
    const unsigned FULL = 0xffffffffu;

    // per-lane joint parameters
    int jj = 0; float w = 0.f;
    float sp0 = 0, sp1 = 0, sp2 = 0, rv0 = 0, rv1 = 0, rv2 = 0;
    float a0c = 0, a1c = 0, a2c = 0;   // mv*rv precomputed
    const bool act = (lane < 24);
    if (act) {
        jj = c_j[lane] * 3;
        w  = c_wl[lane];
        sp0 = stdv[jj];     sp1 = stdv[jj + 1];     sp2 = stdv[jj + 2];
        rv0 = 1.0f / stdv[72 + jj];
        rv1 = 1.0f / stdv[72 + jj + 1];
        rv2 = 1.0f / stdv[72 + jj + 2];
        a0c = meanv[72 + jj]     * rv0;
        a1c = meanv[72 + jj + 1] * rv1;
        a2c = meanv[72 + jj + 2] * rv2;
    }
    int pidx = -1;
    if      (lane == 0)  pidx = 0;
    else if (lane == 8)  pidx = 1;
    else if (lane == 12) pidx = 2;
    else if (lane == 16) pidx = 3;
    else if (lane == 20) pidx = 4;
    float mfrf = 0.f, rf = 0.f;
    if (pidx >= 0) {
        rf = 1.0f / stdv[144 + pidx];
        mfrf = meanv[144 + pidx] * rf;
    }

    float accA = 0.f, accB = 0.f, accC = 0.f;
    float p0 = 0.f, p1 = 0.f, p2 = 0.f;

    // running pointers
    const float* r  = pred + ((size_t)(b * S_ + s0)) * F_;   // row s0
    const float* tr = tvft + ((size_t)(b * (S_ + 1) + s0)) * VF_ + (pidx >= 0 ? pidx : 0);

    int sBeg = s0;
    if (s0 == 0) {
        if (act) {
            p0 = r[jj]; p1 = r[jj + 1]; p2 = r[jj + 2];
            const float q0 = r[77 + jj], q1 = r[78 + jj], q2 = r[79 + jj];
            accB = q0 * q0 + q1 * q1 + q2 * q2;   // s==0 zero-target term
        }
        sBeg = 1;
        r  += F_;
        tr += VF_;
    } else if (act) {
        const float* rp = r - F_;
        p0 = rp[jj]; p1 = rp[jj + 1]; p2 = rp[jj + 2];
    }

    const int sEnd = s0 + CH;
    int s = sBeg;

    // main loop: 4-row batches
    for (; s + 4 <= sEnd; s += 4) {
        float c0[4], c1[4], c2[4], q0[4], q1[4], q2[4];
        {
            const float* rr = r;
            #pragma unroll
            for (int k = 0; k < 4; ++k, rr += F_) {
                if (act) {
                    c0[k] = rr[jj];      c1[k] = rr[jj + 1];  c2[k] = rr[jj + 2];
                    q0[k] = rr[77 + jj]; q1[k] = rr[78 + jj]; q2[k] = rr[79 + jj];
                }
            }
        }
        float trv[4] = {0.f, 0.f, 0.f, 0.f};
        if (pidx >= 0) {
            #pragma unroll
            for (int k = 0; k < 4; ++k) trv[k] = tr[k * VF_];
        }
        float contrib[4];
        #pragma unroll
        for (int k = 0; k < 4; ++k) {
            contrib[k] = 0.f;
            if (act) {
                const float v0 = (c0[k] - p0) * sp0;
                const float v1 = (c1[k] - p1) * sp1;
                const float v2 = (c2[k] - p2) * sp2;
                const float d0 = q0[k] + a0c - v0 * rv0;   // q - (v-mv)*rv
                const float d1 = q1[k] + a1c - v1 * rv1;
                const float d2 = q2[k] + a2c - v2 * rv2;
                accA += d0 * d0 + d1 * d1 + d2 * d2;
                contrib[k] = sqrtf(v0 * v0 + v1 * v1 + v2 * v2) * w;
                p0 = c0[k]; p1 = c1[k]; p2 = c2[k];
            }
        }
        float g4v[4], g8v[4];
        #pragma unroll
        for (int k = 0; k < 4; ++k) g4v[k] = contrib[k] + __shfl_xor_sync(FULL, contrib[k], 1);
        #pragma unroll
        for (int k = 0; k < 4; ++k) g4v[k] += __shfl_xor_sync(FULL, g4v[k], 2);
        #pragma unroll
        for (int k = 0; k < 4; ++k) g8v[k] = g4v[k] + __shfl_xor_sync(FULL, g4v[k], 4);
        if (pidx >= 0) {
            #pragma unroll
            for (int k = 0; k < 4; ++k) {
                const float f = (pidx == 0) ? g8v[k] : g4v[k];
                const float d = trv[k] + mfrf - f * rf;
                accC += d * d;
            }
        }
        r  += 4 * F_;
        tr += 4 * VF_;
    }

    // tail (only the s0==0 chunk: 3 rows)
    for (; s < sEnd; ++s, r += F_, tr += VF_) {
        float contrib = 0.f;
        if (act) {
            const float cc0 = r[jj], cc1 = r[jj + 1], cc2 = r[jj + 2];
            const float qq0 = r[77 + jj], qq1 = r[78 + jj], qq2 = r[79 + jj];
            const float v0 = (cc0 - p0) * sp0;
            const float v1 = (cc1 - p1) * sp1;
            const float v2 = (cc2 - p2) * sp2;
            const float d0 = qq0 + a0c - v0 * rv0;
            const float d1 = qq1 + a1c - v1 * rv1;
            const float d2 = qq2 + a2c - v2 * rv2;
            accA += d0 * d0 + d1 * d1 + d2 * d2;
            contrib = sqrtf(v0 * v0 + v1 * v1 + v2 * v2) * w;
            p0 = cc0; p1 = cc1; p2 = cc2;
        }
        float g4v = contrib;
        g4v += __shfl_xor_sync(FULL, g4v, 1);
        g4v += __shfl_xor_sync(FULL, g4v, 2);
        const float g8v = g4v + __shfl_xor_sync(FULL, g4v, 4);
        if (pidx >= 0) {
            const float f = (pidx == 0) ? g8v : g4v;
            const float d = tr[0] + mfrf - f * rf;
            accC += d * d;
        }
    }

    // ---- reductions ----
    #pragma unroll
    for (int off = 16; off; off >>= 1) {
        accA += __shfl_xor_sync(FULL, accA, off);
        accB += __shfl_xor_sync(FULL, accB, off);
        accC += __shfl_xor_sync(FULL, accC, off);
    }

    __shared__ double sA[WPB], sB[WPB], sC[WPB];
    if (lane == 0) {
        sA[warp] = (double)accA;
        sB[warp] = (double)accB;
        sC[warp] = (double)accC;
    }
    __syncthreads();

    if (warp == 0) {
        double a  = (lane < WPB) ? sA[lane] : 0.0;
        double bb = (lane < WPB) ? sB[lane] : 0.0;
        double c  = (lane < WPB) ? sC[lane] : 0.0;
        #pragma unroll
        for (int off = 4; off; off >>= 1) {
            a  += __shfl_xor_sync(FULL, a, off);
            bb += __shfl_xor_sync(FULL, bb, off);
            c  += __shfl_xor_sync(FULL, c, off);
        }
        if (lane == 0) {
            atomicAdd(&g_acc[0], a);
            atomicAdd(&g_acc[1], bb);
            atomicAdd(&g_acc[2], c);
            __threadfence();
            const unsigned t = atomicAdd(&g_ticket, 1u);
            if (t == (unsigned)(NBLK - 1)) {
                __threadfence();
                volatile double* ga = g_acc;
                const double A  = ga[0];
                const double B0 = ga[1];
                const double C  = ga[2];
                const double nA  = (double)B_ * (double)(S_ - 1) * 72.0;
                const double nB2 = (double)B_ * 72.0;
                const double nC  = (double)B_ * (double)(S_ - 1) * (double)VF_;
                const double loss1 = 10.0 * A / nA + 20.0 * B0 / nB2;
                const double loss2 = 10.0 * C / nC;
                out[0] = (float)(2.0 * loss1 + 1.5 * loss2);
                ga[0] = 0.0; ga[1] = 0.0; ga[2] = 0.0;
                g_ticket = 0;
            }
        }
    }
}

extern "C" void kernel_launch(void* const* d_in, const int* in_sizes, int n_in,
                              void* d_out, int out_size) {
    const float* pred = (const float*)d_in[0];   // predict_seq (B,S,F)
    // d_in[1] = _train_x1 (unused), d_in[2] = _train_x2 (unused)
    const float* tvft = (const float*)d_in[3];   // _true_vel_factor (B,S+1,VF)
    const float* mean = (const float*)d_in[4];   // _mean (F,)
    const float* stdv = (const float*)d_in[5];   // _std (F,)

    vel_loss_ch8<<<NBLK, 256>>>(pred, tvft, mean, stdv, (float*)d_out);
}

// round 10
// speedup vs baseline: 1.2586x; 1.2586x over previous
#include <cuda_runtime.h>

// VelocityLoss on GB300 — R8 dataflow (CH=16, direct LDG, joint-per-lane),
// occupancy push: 2-row batches + __launch_bounds__(256,5) -> <=51 regs
// -> 40 resident warps/SM (vs 32 at 64 regs). Batch row offsets are
// compile-time constants so addressing folds into LDG immediates.

namespace {
constexpr int B_  = 512;
constexpr int S_  = 480;
constexpr int F_  = 149;
constexpr int VF_ = 5;
constexpr int CH  = 16;                   // rows per warp chunk
constexpr int CPB = S_ / CH;              // 30
constexpr int WPB = 8;                    // 256 threads
constexpr int NBLK = B_ * CPB / WPB;      // 1920
}

__device__ double g_acc[3] = {0.0, 0.0, 0.0};
__device__ unsigned int g_ticket = 0;

// lane -> joint, part groups shuffle-aligned:
// lanes 0-7 part0, 8-11 part1, 12-15 part2, 16-19 part3, 20-23 part4
__constant__ int c_j[24] = {
    8, 9, 10, 11, 12, 21, 22, 23,
    0, 1, 2, 3,
    4, 5, 6, 7,
    13, 14, 15, 16,
    17, 18, 19, 20
};
__constant__ float c_wl[24] = {
    1.f/9, 1.f/9, 1.f/9, 1.f/9, 1.f/9, 1.f/9, 2.f/9, 1.f/9,
    0.1f, 0.2f, 0.3f, 0.4f,
    0.1f, 0.2f, 0.3f, 0.4f,
    0.1f, 0.2f, 0.3f, 0.4f,
    0.1f, 0.2f, 0.3f, 0.4f
};

__global__ void __launch_bounds__(256, 5) vel_loss_occ5(
    const float* __restrict__ pred,   // (B, S, F)
    const float* __restrict__ tvft,   // (B, S+1, VF)
    const float* __restrict__ meanv,  // (F,)
    const float* __restrict__ stdv,   // (F,)
    float* __restrict__ out)
{
    const int tid  = threadIdx.x;
    const int lane = tid & 31;
    const int warp = tid >> 5;
    const int idx  = blockIdx.x * WPB + warp;
    const int b    = idx / CPB;
    const int s0   = (idx % CPB) * CH;
    const unsigned FULL = 0xffffffffu;

    // per-lane joint parameters
    int jj = 0; float w = 0.f;
    float sp0 = 0, sp1 = 0, sp2 = 0, rv0 = 0, rv1 = 0, rv2 = 0;
    float a0c = 0, a1c = 0, a2c = 0;   // mv*rv precomputed
    const bool act = (lane < 24);
    if (act) {
        jj = c_j[lane] * 3;
        w  = c_wl[lane];
        sp0 = stdv[jj];     sp1 = stdv[jj + 1];     sp2 = stdv[jj + 2];
        rv0 = 1.0f / stdv[72 + jj];
        rv1 = 1.0f / stdv[72 + jj + 1];
        rv2 = 1.0f / stdv[72 + jj + 2];
        a0c = meanv[72 + jj]     * rv0;
        a1c = meanv[72 + jj + 1] * rv1;
        a2c = meanv[72 + jj + 2] * rv2;
    }
    int pidx = -1;
    if      (lane == 0)  pidx = 0;
    else if (lane == 8)  pidx = 1;
    else if (lane == 12) pidx = 2;
    else if (lane == 16) pidx = 3;
    else if (lane == 20) pidx = 4;
    float mfrf = 0.f, rf = 0.f;
    if (pidx >= 0) {
        rf = 1.0f / stdv[144 + pidx];
        mfrf = meanv[144 + pidx] * rf;
    }

    float accA = 0.f, accB = 0.f, accC = 0.f;
    float p0 = 0.f, p1 = 0.f, p2 = 0.f;

    // running pointers (advanced once per batch; in-batch offsets are consts)
    const float* r  = pred + ((size_t)(b * S_ + s0)) * F_;
    const float* tr = tvft + ((size_t)(b * (S_ + 1) + s0)) * VF_ + (pidx >= 0 ? pidx : 0);

    int sBeg = s0;
    if (s0 == 0) {
        if (act) {
            p0 = r[jj]; p1 = r[jj + 1]; p2 = r[jj + 2];
            const float q0 = r[77 + jj], q1 = r[78 + jj], q2 = r[79 + jj];
            accB = q0 * q0 + q1 * q1 + q2 * q2;   // s==0 zero-target term
        }
        sBeg = 1;
        r  += F_;
        tr += VF_;
    } else if (act) {
        const float* rp = r - F_;
        p0 = rp[jj]; p1 = rp[jj + 1]; p2 = rp[jj + 2];
    }

    const int sEnd = s0 + CH;
    int s = sBeg;

    // main loop: 2-row batches (compile-time in-batch offsets)
    for (; s + 2 <= sEnd; s += 2) {
        float c0[2], c1[2], c2[2], q0[2], q1[2], q2[2];
        #pragma unroll
        for (int k = 0; k < 2; ++k) {
            if (act) {
                c0[k] = r[k * F_ + jj];
                c1[k] = r[k * F_ + jj + 1];
                c2[k] = r[k * F_ + jj + 2];
                q0[k] = r[k * F_ + 77 + jj];
                q1[k] = r[k * F_ + 78 + jj];
                q2[k] = r[k * F_ + 79 + jj];
            }
        }
        float trv[2] = {0.f, 0.f};
        if (pidx >= 0) { trv[0] = tr[0]; trv[1] = tr[VF_]; }

        float contrib[2];
        #pragma unroll
        for (int k = 0; k < 2; ++k) {
            contrib[k] = 0.f;
            if (act) {
                const float v0 = (c0[k] - p0) * sp0;
                const float v1 = (c1[k] - p1) * sp1;
                const float v2 = (c2[k] - p2) * sp2;
                const float d0 = q0[k] + a0c - v0 * rv0;   // q - (v-mv)*rv
                const float d1 = q1[k] + a1c - v1 * rv1;
                const float d2 = q2[k] + a2c - v2 * rv2;
                accA += d0 * d0 + d1 * d1 + d2 * d2;
                contrib[k] = sqrtf(v0 * v0 + v1 * v1 + v2 * v2) * w;
                p0 = c0[k]; p1 = c1[k]; p2 = c2[k];
            }
        }
        float g4v[2], g8v[2];
        #pragma unroll
        for (int k = 0; k < 2; ++k) g4v[k] = contrib[k] + __shfl_xor_sync(FULL, contrib[k], 1);
        #pragma unroll
        for (int k = 0; k < 2; ++k) g4v[k] += __shfl_xor_sync(FULL, g4v[k], 2);
        #pragma unroll
        for (int k = 0; k < 2; ++k) g8v[k] = g4v[k] + __shfl_xor_sync(FULL, g4v[k], 4);
        if (pidx >= 0) {
            #pragma unroll
            for (int k = 0; k < 2; ++k) {
                const float f = (pidx == 0) ? g8v[k] : g4v[k];
                const float d = trv[k] + mfrf - f * rf;
                accC += d * d;
            }
        }
        r  += 2 * F_;
        tr += 2 * VF_;
    }

    // tail (only the s0==0 chunk: 1 row)
    for (; s < sEnd; ++s, r += F_, tr += VF_) {
        float contrib = 0.f;
        if (act) {
            const float cc0 = r[jj], cc1 = r[jj + 1], cc2 = r[jj + 2];
            const float qq0 = r[77 + jj], qq1 = r[78 + jj], qq2 = r[79 + jj];
            const float v0 = (cc0 - p0) * sp0;
            const float v1 = (cc1 - p1) * sp1;
            const float v2 = (cc2 - p2) * sp2;
            const float d0 = qq0 + a0c - v0 * rv0;
            const float d1 = qq1 + a1c - v1 * rv1;
            const float d2 = qq2 + a2c - v2 * rv2;
            accA += d0 * d0 + d1 * d1 + d2 * d2;
            contrib = sqrtf(v0 * v0 + v1 * v1 + v2 * v2) * w;
            p0 = cc0; p1 = cc1; p2 = cc2;
        }
        float g4v = contrib;
        g4v += __shfl_xor_sync(FULL, g4v, 1);
        g4v += __shfl_xor_sync(FULL, g4v, 2);
        const float g8v = g4v + __shfl_xor_sync(FULL, g4v, 4);
        if (pidx >= 0) {
            const float f = (pidx == 0) ? g8v : g4v;
            const float d = tr[0] + mfrf - f * rf;
            accC += d * d;
        }
    }

    // ---- reductions ----
    #pragma unroll
    for (int off = 16; off; off >>= 1) {
        accA += __shfl_xor_sync(FULL, accA, off);
        accB += __shfl_xor_sync(FULL, accB, off);
        accC += __shfl_xor_sync(FULL, accC, off);
    }

    __shared__ double sA[WPB], sB[WPB], sC[WPB];
    if (lane == 0) {
        sA[warp] = (double)accA;
        sB[warp] = (double)accB;
        sC[warp] = (double)accC;
    }
    __syncthreads();

    if (warp == 0) {
        double a  = (lane < WPB) ? sA[lane] : 0.0;
        double bb = (lane < WPB) ? sB[lane] : 0.0;
        double c  = (lane < WPB) ? sC[lane] : 0.0;
        #pragma unroll
        for (int off = 4; off; off >>= 1) {
            a  += __shfl_xor_sync(FULL, a, off);
            bb += __shfl_xor_sync(FULL, bb, off);
            c  += __shfl_xor_sync(FULL, c, off);
        }
        if (lane == 0) {
            atomicAdd(&g_acc[0], a);
            atomicAdd(&g_acc[1], bb);
            atomicAdd(&g_acc[2], c);
            __threadfence();
            const unsigned t = atomicAdd(&g_ticket, 1u);
            if (t == (unsigned)(NBLK - 1)) {
                __threadfence();
                volatile double* ga = g_acc;
                const double A  = ga[0];
                const double B0 = ga[1];
                const double C  = ga[2];
                const double nA  = (double)B_ * (double)(S_ - 1) * 72.0;
                const double nB2 = (double)B_ * 72.0;
                const double nC  = (double)B_ * (double)(S_ - 1) * (double)VF_;
                const double loss1 = 10.0 * A / nA + 20.0 * B0 / nB2;
                const double loss2 = 10.0 * C / nC;
                out[0] = (float)(2.0 * loss1 + 1.5 * loss2);
                ga[0] = 0.0; ga[1] = 0.0; ga[2] = 0.0;
                g_ticket = 0;
            }
        }
    }
}

extern "C" void kernel_launch(void* const* d_in, const int* in_sizes, int n_in,
                              void* d_out, int out_size) {
    const float* pred = (const float*)d_in[0];   // predict_seq (B,S,F)
    // d_in[1] = _train_x1 (unused), d_in[2] = _train_x2 (unused)
    const float* tvft = (const float*)d_in[3];   // _true_vel_factor (B,S+1,VF)
    const float* mean = (const float*)d_in[4];   // _mean (F,)
    const float* stdv = (const float*)d_in[5];   // _std (F,)

    vel_loss_occ5<<<NBLK, 256>>>(pred, tvft, mean, stdv, (float*)d_out);
}

// round 11
// speedup vs baseline: 1.2805x; 1.0174x over previous
#include <cuda_runtime.h>
#include <cstdint>

// VelocityLoss on GB300 — per-warp cp.async pipeline.
// Each warp streams its CH=16 rows through a triple-buffered smem slab:
// stage = 2 rows (1192B) loaded with 16B cp.async.cg from an aligned-down
// window; compute consumes via bank-conflict-free LDS. No block barriers in
// the mainloop (this is what R3's staging got wrong); only per-warp
// wait_group + syncwarp. Consumer never waits on DRAM directly.

namespace {
constexpr int B_  = 512;
constexpr int S_  = 480;
constexpr int F_  = 149;
constexpr int VF_ = 5;
constexpr int CH  = 16;                   // rows per warp chunk
constexpr int CPB = S_ / CH;              // 30
constexpr int WPB = 8;                    // 256 threads
constexpr int NBLK = B_ * CPB / WPB;      // 1920
constexpr int STG_FLOATS = 304;           // 1216B: covers delta(<=12B)+1192B
}

__device__ double g_acc[3] = {0.0, 0.0, 0.0};
__device__ unsigned int g_ticket = 0;

// lane -> joint, part groups shuffle-aligned:
// lanes 0-7 part0, 8-11 part1, 12-15 part2, 16-19 part3, 20-23 part4
__constant__ int c_j[24] = {
    8, 9, 10, 11, 12, 21, 22, 23,
    0, 1, 2, 3,
    4, 5, 6, 7,
    13, 14, 15, 16,
    17, 18, 19, 20
};
__constant__ float c_wl[24] = {
    1.f/9, 1.f/9, 1.f/9, 1.f/9, 1.f/9, 1.f/9, 2.f/9, 1.f/9,
    0.1f, 0.2f, 0.3f, 0.4f,
    0.1f, 0.2f, 0.3f, 0.4f,
    0.1f, 0.2f, 0.3f, 0.4f,
    0.1f, 0.2f, 0.3f, 0.4f
};

__device__ __forceinline__ void cp16(unsigned sdst, const void* gsrc) {
    asm volatile("cp.async.cg.shared.global [%0], [%1], 16;" :: "r"(sdst), "l"(gsrc));
}
__device__ __forceinline__ void cp4(unsigned sdst, const void* gsrc) {
    asm volatile("cp.async.ca.shared.global [%0], [%1], 4;" :: "r"(sdst), "l"(gsrc));
}

__global__ void __launch_bounds__(256, 5) vel_loss_async(
    const float* __restrict__ pred,   // (B, S, F)
    const float* __restrict__ tvft,   // (B, S+1, VF)
    const float* __restrict__ meanv,  // (F,)
    const float* __restrict__ stdv,   // (F,)
    float* __restrict__ out)
{
    __shared__ __align__(16) float stg[WPB][3][STG_FLOATS];
    __shared__ double sA[WPB], sB[WPB], sC[WPB];

    const int tid  = threadIdx.x;
    const int lane = tid & 31;
    const int warp = tid >> 5;
    const int idx  = blockIdx.x * WPB + warp;
    const int b    = idx / CPB;
    const int s0   = (idx % CPB) * CH;
    const unsigned FULL = 0xffffffffu;

    const unsigned sbase = (unsigned)__cvta_generic_to_shared(&stg[warp][0][0]);

    // per-lane joint parameters
    int jj = 0; float w = 0.f;
    float sp0 = 0, sp1 = 0, sp2 = 0, rv0 = 0, rv1 = 0, rv2 = 0;
    float a0c = 0, a1c = 0, a2c = 0;   // mv*rv precomputed
    const bool act = (lane < 24);
    if (act) {
        jj = c_j[lane] * 3;
        w  = c_wl[lane];
        sp0 = stdv[jj];     sp1 = stdv[jj + 1];     sp2 = stdv[jj + 2];
        rv0 = 1.0f / stdv[72 + jj];
        rv1 = 1.0f / stdv[72 + jj + 1];
        rv2 = 1.0f / stdv[72 + jj + 2];
        a0c = meanv[72 + jj]     * rv0;
        a1c = meanv[72 + jj + 1] * rv1;
        a2c = meanv[72 + jj + 2] * rv2;
    }
    int pidx = -1;
    if      (lane == 0)  pidx = 0;
    else if (lane == 8)  pidx = 1;
    else if (lane == 12) pidx = 2;
    else if (lane == 16) pidx = 3;
    else if (lane == 20) pidx = 4;
    float mfrf = 0.f, rf = 0.f;
    if (pidx >= 0) {
        rf = 1.0f / stdv[144 + pidx];
        mfrf = meanv[144 + pidx] * rf;
    }

    float accA = 0.f, accB = 0.f, accC = 0.f;
    float p0 = 0.f, p1 = 0.f, p2 = 0.f;

    const float* tr = tvft + ((size_t)(b * (S_ + 1) + s0)) * VF_ + (pidx >= 0 ? pidx : 0);

    // ---- prologue: prev-row positions (plain LDG) / s==0 zero-target term ----
    int sBeg = s0;
    {
        const float* r0 = pred + ((size_t)(b * S_ + s0)) * F_;
        if (s0 == 0) {
            if (act) {
                p0 = r0[jj]; p1 = r0[jj + 1]; p2 = r0[jj + 2];
                const float q0 = r0[77 + jj], q1 = r0[78 + jj], q2 = r0[79 + jj];
                accB = q0 * q0 + q1 * q1 + q2 * q2;
            }
            sBeg = 1;
            tr += VF_;
        } else if (act) {
            const float* rp = r0 - F_;
            p0 = rp[jj]; p1 = rp[jj + 1]; p2 = rp[jj + 2];
        }
    }

    // ---- stage loader: rows s, s+1 -> slab sl ----
    auto loadStage = [&](int s, int sl) {
        const size_t fbase = (size_t)(b * S_ + s) * F_;
        const uintptr_t gb = (uintptr_t)(pred + fbase);
        const char* ga = (const char*)(gb & ~(uintptr_t)15);
        const int db = (int)(gb & 15);
        const int nbytes = db + 2 * F_ * 4;
        const unsigned sdst = sbase + (unsigned)(sl * STG_FLOATS * 4);
        const bool risky = (b == B_ - 1) && (s + 2 >= S_);   // 16B window would pass buffer end
        if (!risky) {
            const int nch = (nbytes + 15) >> 4;
            for (int i = lane; i < nch; i += 32)
                cp16(sdst + i * 16, ga + i * 16);
        } else {
            const int nw = nbytes >> 2;                      // db%4==0 -> exact
            for (int i = lane; i < nw; i += 32)
                cp4(sdst + i * 4, ga + i * 4);
        }
        asm volatile("cp.async.commit_group;");
    };

    // ---- consume one 2-row batch from slab sl ----
    auto computeBatch = [&](int s, int sl) {
        const int df = (int)(((size_t)(b * S_ + s) * F_) & 3);
        const float* r0 = &stg[warp][sl][0] + df;
        const float* r1 = r0 + F_;
        float trv0 = 0.f, trv1 = 0.f;
        if (pidx >= 0) { trv0 = tr[0]; trv1 = tr[VF_]; }

        float contrib[2];
        const float* rr = r0;
        #pragma unroll
        for (int k = 0; k < 2; ++k) {
            contrib[k] = 0.f;
            if (act) {
                const float c0 = rr[jj], c1 = rr[jj + 1], c2 = rr[jj + 2];
                const float q0 = rr[77 + jj], q1 = rr[78 + jj], q2 = rr[79 + jj];
                const float v0 = (c0 - p0) * sp0;
                const float v1 = (c1 - p1) * sp1;
                const float v2 = (c2 - p2) * sp2;
                const float d0 = q0 + a0c - v0 * rv0;
                const float d1 = q1 + a1c - v1 * rv1;
                const float d2 = q2 + a2c - v2 * rv2;
                accA += d0 * d0 + d1 * d1 + d2 * d2;
                contrib[k] = sqrtf(v0 * v0 + v1 * v1 + v2 * v2) * w;
                p0 = c0; p1 = c1; p2 = c2;
            }
            rr = r1;
        }
        float g4v[2], g8v[2];
        #pragma unroll
        for (int k = 0; k < 2; ++k) g4v[k] = contrib[k] + __shfl_xor_sync(FULL, contrib[k], 1);
        #pragma unroll
        for (int k = 0; k < 2; ++k) g4v[k] += __shfl_xor_sync(FULL, g4v[k], 2);
        #pragma unroll
        for (int k = 0; k < 2; ++k) g8v[k] = g4v[k] + __shfl_xor_sync(FULL, g4v[k], 4);
        if (pidx >= 0) {
            const float f0 = (pidx == 0) ? g8v[0] : g4v[0];
            const float f1 = (pidx == 0) ? g8v[1] : g4v[1];
            const float e0 = trv0 + mfrf - f0 * rf;
            const float e1 = trv1 + mfrf - f1 * rf;
            accC += e0 * e0 + e1 * e1;
        }
        tr += 2 * VF_;
    };

    // ---- pipelined mainloop (depth 3, per-warp only) ----
    const int sEnd = s0 + CH;
    const int nBat = (sEnd - sBeg) >> 1;      // 8, or 7 for the s0==0 chunk
    loadStage(sBeg, 0);
    loadStage(sBeg + 2, 1);
    for (int t = 0; t < nBat; ++t) {
        if (t + 2 < nBat) loadStage(sBeg + (t + 2) * 2, (t + 2) % 3);
        if (t + 3 <= nBat)      asm volatile("cp.async.wait_group 2;");
        else if (t + 2 == nBat) asm volatile("cp.async.wait_group 1;");
        else                    asm volatile("cp.async.wait_group 0;");
        __syncwarp();
        computeBatch(sBeg + t * 2, t % 3);
    }

    // tail row (only the s0==0 chunk: s = 15), plain LDG
    if (sBeg + nBat * 2 < sEnd) {
        const int s = sBeg + nBat * 2;
        const float* r = pred + ((size_t)(b * S_ + s)) * F_;
        float contrib = 0.f;
        if (act) {
            const float c0 = r[jj], c1 = r[jj + 1], c2 = r[jj + 2];
            const float q0 = r[77 + jj], q1 = r[78 + jj], q2 = r[79 + jj];
            const float v0 = (c0 - p0) * sp0;
            const float v1 = (c1 - p1) * sp1;
            const float v2 = (c2 - p2) * sp2;
            const float d0 = q0 + a0c - v0 * rv0;
            const float d1 = q1 + a1c - v1 * rv1;
            const float d2 = q2 + a2c - v2 * rv2;
            accA += d0 * d0 + d1 * d1 + d2 * d2;
            contrib = sqrtf(v0 * v0 + v1 * v1 + v2 * v2) * w;
        }
        float g4v = contrib;
        g4v += __shfl_xor_sync(FULL, g4v, 1);
        g4v += __shfl_xor_sync(FULL, g4v, 2);
        const float g8v = g4v + __shfl_xor_sync(FULL, g4v, 4);
        if (pidx >= 0) {
            const float f = (pidx == 0) ? g8v : g4v;
            const float d = tr[0] + mfrf - f * rf;
            accC += d * d;
        }
    }

    // ---- reductions ----
    #pragma unroll
    for (int off = 16; off; off >>= 1) {
        accA += __shfl_xor_sync(FULL, accA, off);
        accB += __shfl_xor_sync(FULL, accB, off);
        accC += __shfl_xor_sync(FULL, accC, off);
    }
    if (lane == 0) {
        sA[warp] = (double)accA;
        sB[warp] = (double)accB;
        sC[warp] = (double)accC;
    }
    __syncthreads();

    if (warp == 0) {
        double a  = (lane < WPB) ? sA[lane] : 0.0;
        double bb = (lane < WPB) ? sB[lane] : 0.0;
        double c  = (lane < WPB) ? sC[lane] : 0.0;
        #pragma unroll
        for (int off = 4; off; off >>= 1) {
            a  += __shfl_xor_sync(FULL, a, off);
            bb += __shfl_xor_sync(FULL, bb, off);
            c  += __shfl_xor_sync(FULL, c, off);
        }
        if (lane == 0) {
            atomicAdd(&g_acc[0], a);
            atomicAdd(&g_acc[1], bb);
            atomicAdd(&g_acc[2], c);
            __threadfence();
            const unsigned t = atomicAdd(&g_ticket, 1u);
            if (t == (unsigned)(NBLK - 1)) {
                __threadfence();
                volatile double* ga = g_acc;
                const double A  = ga[0];
                const double B0 = ga[1];
                const double C  = ga[2];
                const double nA  = (double)B_ * (double)(S_ - 1) * 72.0;
                const double nB2 = (double)B_ * 72.0;
                const double nC  = (double)B_ * (double)(S_ - 1) * (double)VF_;
                const double loss1 = 10.0 * A / nA + 20.0 * B0 / nB2;
                const double loss2 = 10.0 * C / nC;
                out[0] = (float)(2.0 * loss1 + 1.5 * loss2);
                ga[0] = 0.0; ga[1] = 0.0; ga[2] = 0.0;
                g_ticket = 0;
            }
        }
    }
}

extern "C" void kernel_launch(void* const* d_in, const int* in_sizes, int n_in,
                              void* d_out, int out_size) {
    const float* pred = (const float*)d_in[0];   // predict_seq (B,S,F)
    // d_in[1] = _train_x1 (unused), d_in[2] = _train_x2 (unused)
    const float* tvft = (const float*)d_in[3];   // _true_vel_factor (B,S+1,VF)
    const float* mean = (const float*)d_in[4];   // _mean (F,)
    const float* stdv = (const float*)d_in[5];   // _std (F,)

    vel_loss_async<<<NBLK, 256>>>(pred, tvft, mean, stdv, (float*)d_out);
}

// round 12
// speedup vs baseline: 1.4518x; 1.1338x over previous
#include <cuda_runtime.h>
#include <cstdint>

// VelocityLoss on GB300 — per-warp cp.async pipeline, flattened:
// 4-row stages, depth 2, FULLY UNROLLED mainloop (compile-time slab ids and
// wait_group immediates; no %3, no runtime wait selection). Cuts the ~3x
// instruction bloat R11 showed (120 instr/row vs ~37 floor).

namespace {
constexpr int B_  = 512;
constexpr int S_  = 480;
constexpr int F_  = 149;
constexpr int VF_ = 5;
constexpr int CH  = 16;                   // rows per warp chunk
constexpr int CPB = S_ / CH;              // 30
constexpr int WPB = 8;                    // 256 threads
constexpr int NBLK = B_ * CPB / WPB;      // 1920
constexpr int STG_FLOATS = 608;           // 2432B: delta(<=12B) + 4*596B, 16B mult
}

__device__ double g_acc[3] = {0.0, 0.0, 0.0};
__device__ unsigned int g_ticket = 0;

// lane -> joint, part groups shuffle-aligned:
// lanes 0-7 part0, 8-11 part1, 12-15 part2, 16-19 part3, 20-23 part4
__constant__ int c_j[24] = {
    8, 9, 10, 11, 12, 21, 22, 23,
    0, 1, 2, 3,
    4, 5, 6, 7,
    13, 14, 15, 16,
    17, 18, 19, 20
};
__constant__ float c_wl[24] = {
    1.f/9, 1.f/9, 1.f/9, 1.f/9, 1.f/9, 1.f/9, 2.f/9, 1.f/9,
    0.1f, 0.2f, 0.3f, 0.4f,
    0.1f, 0.2f, 0.3f, 0.4f,
    0.1f, 0.2f, 0.3f, 0.4f,
    0.1f, 0.2f, 0.3f, 0.4f
};

__device__ __forceinline__ void cp16(unsigned sdst, const void* gsrc) {
    asm volatile("cp.async.cg.shared.global [%0], [%1], 16;" :: "r"(sdst), "l"(gsrc));
}
__device__ __forceinline__ void cp4(unsigned sdst, const void* gsrc) {
    asm volatile("cp.async.ca.shared.global [%0], [%1], 4;" :: "r"(sdst), "l"(gsrc));
}
__device__ __forceinline__ void commitg() { asm volatile("cp.async.commit_group;"); }
template <int N> __device__ __forceinline__ void waitg() {
    asm volatile("cp.async.wait_group %0;" :: "n"(N));
}

__global__ void __launch_bounds__(256, 5) vel_loss_flat(
    const float* __restrict__ pred,   // (B, S, F)
    const float* __restrict__ tvft,   // (B, S+1, VF)
    const float* __restrict__ meanv,  // (F,)
    const float* __restrict__ stdv,   // (F,)
    float* __restrict__ out)
{
    __shared__ __align__(16) float stg[WPB][2][STG_FLOATS];
    __shared__ double sA[WPB], sB[WPB], sC[WPB];

    const int tid  = threadIdx.x;
    const int lane = tid & 31;
    const int warp = tid >> 5;
    const int idx  = blockIdx.x * WPB + warp;
    const int b    = idx / CPB;
    const int s0   = (idx % CPB) * CH;
    const unsigned FULL = 0xffffffffu;

    const unsigned sbase = (unsigned)__cvta_generic_to_shared(&stg[warp][0][0]);

    // per-lane joint parameters
    int jj = 0; float w = 0.f;
    float sp0 = 0, sp1 = 0, sp2 = 0, rv0 = 0, rv1 = 0, rv2 = 0;
    float a0c = 0, a1c = 0, a2c = 0;   // mv*rv precomputed
    const bool act = (lane < 24);
    if (act) {
        jj = c_j[lane] * 3;
        w  = c_wl[lane];
        sp0 = stdv[jj];     sp1 = stdv[jj + 1];     sp2 = stdv[jj + 2];
        rv0 = 1.0f / stdv[72 + jj];
        rv1 = 1.0f / stdv[72 + jj + 1];
        rv2 = 1.0f / stdv[72 + jj + 2];
        a0c = meanv[72 + jj]     * rv0;
        a1c = meanv[72 + jj + 1] * rv1;
        a2c = meanv[72 + jj + 2] * rv2;
    }
    int pidx = -1;
    if      (lane == 0)  pidx = 0;
    else if (lane == 8)  pidx = 1;
    else if (lane == 12) pidx = 2;
    else if (lane == 16) pidx = 3;
    else if (lane == 20) pidx = 4;
    float mfrf = 0.f, rf = 0.f;
    if (pidx >= 0) {
        rf = 1.0f / stdv[144 + pidx];
        mfrf = meanv[144 + pidx] * rf;
    }

    float accA = 0.f, accB = 0.f, accC = 0.f;
    float p0 = 0.f, p1 = 0.f, p2 = 0.f;

    const float* tr = tvft + ((size_t)(b * (S_ + 1) + s0)) * VF_ + (pidx >= 0 ? pidx : 0);

    // ---- prologue: prev-row positions / s==0 zero-target term (plain LDG) ----
    const bool first = (s0 == 0);
    {
        const float* r0 = pred + ((size_t)(b * S_ + s0)) * F_;
        if (first) {
            if (act) {
                p0 = r0[jj]; p1 = r0[jj + 1]; p2 = r0[jj + 2];
                const float q0 = r0[77 + jj], q1 = r0[78 + jj], q2 = r0[79 + jj];
                accB = q0 * q0 + q1 * q1 + q2 * q2;
            }
            tr += VF_;
        } else if (act) {
            const float* rp = r0 - F_;
            p0 = rp[jj]; p1 = rp[jj + 1]; p2 = rp[jj + 2];
        }
    }
    const int sBeg = first ? 1 : s0;
    // last chunk of the whole tensor: 16B window could pass the buffer end
    const bool lastChunk = (idx == B_ * CPB - 1);

    // ---- stage loader: rows s..s+3 -> slab sl ----
    auto loadStage = [&](int s, int sl) {
        const uintptr_t gb = (uintptr_t)(pred + (size_t)(b * S_ + s) * F_);
        const char* ga = (const char*)(gb & ~(uintptr_t)15);
        const int db = (int)(gb & 15);
        const int nbytes = db + 4 * F_ * 4;
        const unsigned sdst = sbase + (unsigned)(sl * STG_FLOATS * 4);
        if (!lastChunk || s + 4 < S_) {
            const int nch = (nbytes + 15) >> 4;
            for (int i = lane; i < nch; i += 32)
                cp16(sdst + i * 16, ga + i * 16);
        } else {
            const int nw = nbytes >> 2;
            for (int i = lane; i < nw; i += 32)
                cp4(sdst + i * 4, ga + i * 4);
        }
        commitg();
    };

    // ---- consume NR rows of a staged batch ----
    auto computeBatch = [&](int s, int sl, auto nrc) {
        constexpr int NR = decltype(nrc)::value;
        const int df = (int)(((unsigned)(b * S_ + s) * (unsigned)F_) & 3u);
        const float* r0 = &stg[warp][sl][0] + df;
        float trv[NR];
        if (pidx >= 0) {
            #pragma unroll
            for (int k = 0; k < NR; ++k) trv[k] = tr[k * VF_];
        }
        float contrib[NR];
        #pragma unroll
        for (int k = 0; k < NR; ++k) {
            contrib[k] = 0.f;
            if (act) {
                const float* rr = r0 + k * F_;
                const float c0 = rr[jj], c1 = rr[jj + 1], c2 = rr[jj + 2];
                const float q0 = rr[77 + jj], q1 = rr[78 + jj], q2 = rr[79 + jj];
                const float v0 = (c0 - p0) * sp0;
                const float v1 = (c1 - p1) * sp1;
                const float v2 = (c2 - p2) * sp2;
                const float d0 = q0 + a0c - v0 * rv0;
                const float d1 = q1 + a1c - v1 * rv1;
                const float d2 = q2 + a2c - v2 * rv2;
                accA += d0 * d0 + d1 * d1 + d2 * d2;
                contrib[k] = sqrtf(v0 * v0 + v1 * v1 + v2 * v2) * w;
                p0 = c0; p1 = c1; p2 = c2;
            }
        }
        float g4v[NR], g8v[NR];
        #pragma unroll
        for (int k = 0; k < NR; ++k) g4v[k] = contrib[k] + __shfl_xor_sync(FULL, contrib[k], 1);
        #pragma unroll
        for (int k = 0; k < NR; ++k) g4v[k] += __shfl_xor_sync(FULL, g4v[k], 2);
        #pragma unroll
        for (int k = 0; k < NR; ++k) g8v[k] = g4v[k] + __shfl_xor_sync(FULL, g4v[k], 4);
        if (pidx >= 0) {
            #pragma unroll
            for (int k = 0; k < NR; ++k) {
                const float f = (pidx == 0) ? g8v[k] : g4v[k];
                const float d = trv[k] + mfrf - f * rf;
                accC += d * d;
            }
        }
        tr += NR * VF_;
    };

    constexpr auto N4 = std::integral_constant<int, 4>{};
    constexpr auto N3 = std::integral_constant<int, 3>{};

    // ---- fully unrolled pipelined mainloop (depth 2) ----
    loadStage(sBeg, 0);
    loadStage(sBeg + 4, 1);
    waitg<1>(); __syncwarp();
    computeBatch(sBeg, 0, N4);
    loadStage(sBeg + 8, 0);
    waitg<1>(); __syncwarp();
    computeBatch(sBeg + 4, 1, N4);
    if (!first) {
        loadStage(sBeg + 12, 1);
        waitg<1>(); __syncwarp();
        computeBatch(sBeg + 8, 0, N4);
        waitg<0>(); __syncwarp();
        computeBatch(sBeg + 12, 1, N4);
    } else {
        // rows 1..15: batches 4+4+4+3 (the last stage load covers rows 13..16;
        // row 16 exists in this batch row, harmless over-stage)
        loadStage(sBeg + 12, 1);
        waitg<1>(); __syncwarp();
        computeBatch(sBeg + 8, 0, N4);
        waitg<0>(); __syncwarp();
        computeBatch(sBeg + 12, 1, N3);
    }

    // ---- reductions ----
    #pragma unroll
    for (int off = 16; off; off >>= 1) {
        accA += __shfl_xor_sync(FULL, accA, off);
        accB += __shfl_xor_sync(FULL, accB, off);
        accC += __shfl_xor_sync(FULL, accC, off);
    }
    if (lane == 0) {
        sA[warp] = (double)accA;
        sB[warp] = (double)accB;
        sC[warp] = (double)accC;
    }
    __syncthreads();

    if (warp == 0) {
        double a  = (lane < WPB) ? sA[lane] : 0.0;
        double bb = (lane < WPB) ? sB[lane] : 0.0;
        double c  = (lane < WPB) ? sC[lane] : 0.0;
        #pragma unroll
        for (int off = 4; off; off >>= 1) {
            a  += __shfl_xor_sync(FULL, a, off);
            bb += __shfl_xor_sync(FULL, bb, off);
            c  += __shfl_xor_sync(FULL, c, off);
        }
        if (lane == 0) {
            atomicAdd(&g_acc[0], a);
            atomicAdd(&g_acc[1], bb);
            atomicAdd(&g_acc[2], c);
            __threadfence();
            const unsigned t = atomicAdd(&g_ticket, 1u);
            if (t == (unsigned)(NBLK - 1)) {
                __threadfence();
                volatile double* ga = g_acc;
                const double A  = ga[0];
                const double B0 = ga[1];
                const double C  = ga[2];
                const double nA  = (double)B_ * (double)(S_ - 1) * 72.0;
                const double nB2 = (double)B_ * 72.0;
                const double nC  = (double)B_ * (double)(S_ - 1) * (double)VF_;
                const double loss1 = 10.0 * A / nA + 20.0 * B0 / nB2;
                const double loss2 = 10.0 * C / nC;
                out[0] = (float)(2.0 * loss1 + 1.5 * loss2);
                ga[0] = 0.0; ga[1] = 0.0; ga[2] = 0.0;
                g_ticket = 0;
            }
        }
    }
}

extern "C" void kernel_launch(void* const* d_in, const int* in_sizes, int n_in,
                              void* d_out, int out_size) {
    const float* pred = (const float*)d_in[0];   // predict_seq (B,S,F)
    // d_in[1] = _train_x1 (unused), d_in[2] = _train_x2 (unused)
    const float* tvft = (const float*)d_in[3];   // _true_vel_factor (B,S+1,VF)
    const float* mean = (const float*)d_in[4];   // _mean (F,)
    const float* stdv = (const float*)d_in[5];   // _std (F,)

    vel_loss_flat<<<NBLK, 256>>>(pred, tvft, mean, stdv, (float*)d_out);
}

// round 13
// speedup vs baseline: 1.5230x; 1.0491x over previous
#include <cuda_runtime.h>
#include <cstdint>

// VelocityLoss on GB300 — R12 flattened cp.async pipeline +
//  (1) _true_vel_factor staged per chunk via cp.async (80 contiguous floats)
//      -> kills 16 scattered consumer-side LDGs per chunk
//  (2) chunk-invariant loader: df and chunk count are constant across stages
//      (stage stride 2384B % 16 == 0); running aligned pointer; 5-slot
//      compile-time-unrolled predicated cp16 loop.

namespace {
constexpr int B_  = 512;
constexpr int S_  = 480;
constexpr int F_  = 149;
constexpr int VF_ = 5;
constexpr int CH  = 16;                   // rows per warp chunk
constexpr int CPB = S_ / CH;              // 30
constexpr int WPB = 8;                    // 256 threads
constexpr int NBLK = B_ * CPB / WPB;      // 1920
constexpr int STG_FLOATS = 608;           // 2432B: delta(<=12B) + 4*596B
constexpr int TV_FLOATS  = 88;            // delta(<=3) + 80 floats + pad
}

__device__ double g_acc[3] = {0.0, 0.0, 0.0};
__device__ unsigned int g_ticket = 0;

// lane -> joint, part groups shuffle-aligned:
// lanes 0-7 part0, 8-11 part1, 12-15 part2, 16-19 part3, 20-23 part4
__constant__ int c_j[24] = {
    8, 9, 10, 11, 12, 21, 22, 23,
    0, 1, 2, 3,
    4, 5, 6, 7,
    13, 14, 15, 16,
    17, 18, 19, 20
};
__constant__ float c_wl[24] = {
    1.f/9, 1.f/9, 1.f/9, 1.f/9, 1.f/9, 1.f/9, 2.f/9, 1.f/9,
    0.1f, 0.2f, 0.3f, 0.4f,
    0.1f, 0.2f, 0.3f, 0.4f,
    0.1f, 0.2f, 0.3f, 0.4f,
    0.1f, 0.2f, 0.3f, 0.4f
};

__device__ __forceinline__ void cp16(unsigned sdst, const void* gsrc) {
    asm volatile("cp.async.cg.shared.global [%0], [%1], 16;" :: "r"(sdst), "l"(gsrc));
}
__device__ __forceinline__ void cp4(unsigned sdst, const void* gsrc) {
    asm volatile("cp.async.ca.shared.global [%0], [%1], 4;" :: "r"(sdst), "l"(gsrc));
}
__device__ __forceinline__ void commitg() { asm volatile("cp.async.commit_group;"); }
template <int N> __device__ __forceinline__ void waitg() {
    asm volatile("cp.async.wait_group %0;" :: "n"(N));
}

__global__ void __launch_bounds__(256, 5) vel_loss_tv(
    const float* __restrict__ pred,   // (B, S, F)
    const float* __restrict__ tvft,   // (B, S+1, VF)
    const float* __restrict__ meanv,  // (F,)
    const float* __restrict__ stdv,   // (F,)
    float* __restrict__ out)
{
    __shared__ __align__(16) float stg[WPB][2][STG_FLOATS];
    __shared__ __align__(16) float tvs[WPB][TV_FLOATS];
    __shared__ double sA[WPB], sB[WPB], sC[WPB];

    const int tid  = threadIdx.x;
    const int lane = tid & 31;
    const int warp = tid >> 5;
    const int idx  = blockIdx.x * WPB + warp;
    const int b    = idx / CPB;
    const int s0   = (idx % CPB) * CH;
    const unsigned FULL = 0xffffffffu;

    const unsigned sbase  = (unsigned)__cvta_generic_to_shared(&stg[warp][0][0]);
    const unsigned tvbase = (unsigned)__cvta_generic_to_shared(&tvs[warp][0]);

    // per-lane joint parameters
    int jj = 0; float w = 0.f;
    float sp0 = 0, sp1 = 0, sp2 = 0, rv0 = 0, rv1 = 0, rv2 = 0;
    float a0c = 0, a1c = 0, a2c = 0;   // mv*rv precomputed
    const bool act = (lane < 24);
    if (act) {
        jj = c_j[lane] * 3;
        w  = c_wl[lane];
        sp0 = stdv[jj];     sp1 = stdv[jj + 1];     sp2 = stdv[jj + 2];
        rv0 = 1.0f / stdv[72 + jj];
        rv1 = 1.0f / stdv[72 + jj + 1];
        rv2 = 1.0f / stdv[72 + jj + 2];
        a0c = meanv[72 + jj]     * rv0;
        a1c = meanv[72 + jj + 1] * rv1;
        a2c = meanv[72 + jj + 2] * rv2;
    }
    int pidx = -1;
    if      (lane == 0)  pidx = 0;
    else if (lane == 8)  pidx = 1;
    else if (lane == 12) pidx = 2;
    else if (lane == 16) pidx = 3;
    else if (lane == 20) pidx = 4;
    float mfrf = 0.f, rf = 0.f;
    if (pidx >= 0) {
        rf = 1.0f / stdv[144 + pidx];
        mfrf = meanv[144 + pidx] * rf;
    }
    const int pid0 = (pidx >= 0) ? pidx : 0;   // safe in-bounds index for idle lanes

    float accA = 0.f, accB = 0.f, accC = 0.f;
    float p0 = 0.f, p1 = 0.f, p2 = 0.f;

    // ---- prologue: prev-row positions / s==0 zero-target term (plain LDG) ----
    const bool first = (s0 == 0);
    {
        const float* r0 = pred + ((size_t)(b * S_ + s0)) * F_;
        if (first) {
            if (act) {
                p0 = r0[jj]; p1 = r0[jj + 1]; p2 = r0[jj + 2];
                const float q0 = r0[77 + jj], q1 = r0[78 + jj], q2 = r0[79 + jj];
                accB = q0 * q0 + q1 * q1 + q2 * q2;
            }
        } else if (act) {
            const float* rp = r0 - F_;
            p0 = rp[jj]; p1 = rp[jj + 1]; p2 = rp[jj + 2];
        }
    }
    const int sBeg = first ? 1 : s0;
    const bool lastChunk = (idx == B_ * CPB - 1);

    // ---- chunk-invariant loader state (stage stride 2384B % 16 == 0) ----
    const size_t fb0 = (size_t)(b * S_ + sBeg) * F_;
    const uintptr_t gb0 = (uintptr_t)(pred + fb0);
    const char* ga0 = (const char*)(gb0 & ~(uintptr_t)15);
    const int db  = (int)(gb0 & 15);
    const int df  = db >> 2;                        // float offset (pred 16B-aligned base)
    const int nch = (db + 4 * F_ * 4 + 15) >> 4;    // 149 or 150, constant per chunk

    auto loadStage = [&](int t, int sl) {
        const char* ga = ga0 + (size_t)t * (4 * F_ * 4);
        const unsigned sdst = sbase + (unsigned)(sl * STG_FLOATS * 4);
        if (!lastChunk || t < 3) {
            #pragma unroll
            for (int i = 0; i < 5; ++i) {
                const int c = lane + i * 32;
                if (c < nch) cp16(sdst + c * 16, ga + c * 16);
            }
        } else {                                    // final stage of the tensor
            const int nw = (db + 4 * F_ * 4) >> 2;
            for (int i = lane; i < nw; i += 32)
                cp4(sdst + i * 4, ga + i * 4);
        }
        commitg();
    };

    // ---- tv staging: 16 rows x 5 floats, contiguous (proven in-bounds) ----
    const size_t ftv = (size_t)(b * (S_ + 1) + sBeg) * VF_;
    const uintptr_t gtv = (uintptr_t)(tvft + ftv);
    const char* gatv = (const char*)(gtv & ~(uintptr_t)15);
    const int dtv4 = (int)(ftv & 3);
    {
        const int nchTV = ((int)(gtv & 15) + 16 * VF_ * 4 + 15) >> 4;   // <= 21
        if (lane < nchTV) cp16(tvbase + lane * 16, gatv + lane * 16);
    }

    // ---- consume NR rows of a staged batch ----
    auto computeBatch = [&](int j0, int sl, auto nrc) {
        constexpr int NR = decltype(nrc)::value;
        const float* r0 = &stg[warp][sl][0] + df;
        const float* tvp = &tvs[warp][0] + dtv4 + j0 * VF_ + pid0;
        float trv[NR];
        #pragma unroll
        for (int k = 0; k < NR; ++k) trv[k] = tvp[k * VF_];
        float contrib[NR];
        #pragma unroll
        for (int k = 0; k < NR; ++k) {
            contrib[k] = 0.f;
            if (act) {
                const float* rr = r0 + k * F_;
                const float c0 = rr[jj], c1 = rr[jj + 1], c2 = rr[jj + 2];
                const float q0 = rr[77 + jj], q1 = rr[78 + jj], q2 = rr[79 + jj];
                const float v0 = (c0 - p0) * sp0;
                const float v1 = (c1 - p1) * sp1;
                const float v2 = (c2 - p2) * sp2;
                const float d0 = q0 + a0c - v0 * rv0;
                const float d1 = q1 + a1c - v1 * rv1;
                const float d2 = q2 + a2c - v2 * rv2;
                accA += d0 * d0 + d1 * d1 + d2 * d2;
                contrib[k] = sqrtf(v0 * v0 + v1 * v1 + v2 * v2) * w;
                p0 = c0; p1 = c1; p2 = c2;
            }
        }
        float g4v[NR], g8v[NR];
        #pragma unroll
        for (int k = 0; k < NR; ++k) g4v[k] = contrib[k] + __shfl_xor_sync(FULL, contrib[k], 1);
        #pragma unroll
        for (int k = 0; k < NR; ++k) g4v[k] += __shfl_xor_sync(FULL, g4v[k], 2);
        #pragma unroll
        for (int k = 0; k < NR; ++k) g8v[k] = g4v[k] + __shfl_xor_sync(FULL, g4v[k], 4);
        if (pidx >= 0) {
            #pragma unroll
            for (int k = 0; k < NR; ++k) {
                const float f = (pidx == 0) ? g8v[k] : g4v[k];
                const float d = trv[k] + mfrf - f * rf;
                accC += d * d;
            }
        }
    };

    constexpr auto N4 = std::integral_constant<int, 4>{};
    constexpr auto N3 = std::integral_constant<int, 3>{};

    // ---- fully unrolled pipelined mainloop (depth 2; tv rides group 0) ----
    loadStage(0, 0);                    // + tv cp16s issued above, same group
    loadStage(1, 1);
    waitg<1>(); __syncwarp();
    computeBatch(0, 0, N4);
    loadStage(2, 0);
    waitg<1>(); __syncwarp();
    computeBatch(4, 1, N4);
    loadStage(3, 1);
    waitg<1>(); __syncwarp();
    computeBatch(8, 0, N4);
    waitg<0>(); __syncwarp();
    if (!first) computeBatch(12, 1, N4);
    else        computeBatch(12, 1, N3);   // rows 13..15 (stage covers 13..16)

    // ---- reductions ----
    #pragma unroll
    for (int off = 16; off; off >>= 1) {
        accA += __shfl_xor_sync(FULL, accA, off);
        accB += __shfl_xor_sync(FULL, accB, off);
        accC += __shfl_xor_sync(FULL, accC, off);
    }
    if (lane == 0) {
        sA[warp] = (double)accA;
        sB[warp] = (double)accB;
        sC[warp] = (double)accC;
    }
    __syncthreads();

    if (warp == 0) {
        double a  = (lane < WPB) ? sA[lane] : 0.0;
        double bb = (lane < WPB) ? sB[lane] : 0.0;
        double c  = (lane < WPB) ? sC[lane] : 0.0;
        #pragma unroll
        for (int off = 4; off; off >>= 1) {
            a  += __shfl_xor_sync(FULL, a, off);
            bb += __shfl_xor_sync(FULL, bb, off);
            c  += __shfl_xor_sync(FULL, c, off);
        }
        if (lane == 0) {
            atomicAdd(&g_acc[0], a);
            atomicAdd(&g_acc[1], bb);
            atomicAdd(&g_acc[2], c);
            __threadfence();
            const unsigned t = atomicAdd(&g_ticket, 1u);
            if (t == (unsigned)(NBLK - 1)) {
                __threadfence();
                volatile double* ga = g_acc;
                const double A  = ga[0];
                const double B0 = ga[1];
                const double C  = ga[2];
                const double nA  = (double)B_ * (double)(S_ - 1) * 72.0;
                const double nB2 = (double)B_ * 72.0;
                const double nC  = (double)B_ * (double)(S_ - 1) * (double)VF_;
                const double loss1 = 10.0 * A / nA + 20.0 * B0 / nB2;
                const double loss2 = 10.0 * C / nC;
                out[0] = (float)(2.0 * loss1 + 1.5 * loss2);
                ga[0] = 0.0; ga[1] = 0.0; ga[2] = 0.0;
                g_ticket = 0;
            }
        }
    }
}

extern "C" void kernel_launch(void* const* d_in, const int* in_sizes, int n_in,
                              void* d_out, int out_size) {
    const float* pred = (const float*)d_in[0];   // predict_seq (B,S,F)
    // d_in[1] = _train_x1 (unused), d_in[2] = _train_x2 (unused)
    const float* tvft = (const float*)d_in[3];   // _true_vel_factor (B,S+1,VF)
    const float* mean = (const float*)d_in[4];   // _mean (F,)
    const float* stdv = (const float*)d_in[5];   // _std (F,)

    vel_loss_tv<<<NBLK, 256>>>(pred, tvft, mean, stdv, (float*)d_out);
}

// round 14
// speedup vs baseline: 1.6016x; 1.0516x over previous
#include <cuda_runtime.h>
#include <cstdint>
#include <type_traits>

// VelocityLoss on GB300 — dual-chain interleaved cp.async pipeline.
// Each warp owns TWO independent 16-row chunks (A: s0.., B: s0+16..) and
// alternates: wait A-stage, compute A, issue next A; wait B-stage, compute B,
// issue next B. Groups complete in commit order, so waitg<1> always releases
// exactly the stage about to be consumed while keeping one load in flight.
// Each stage gets a full other-chain compute interval to land; two p-chains
// double ILP. Slab per chain is reused (intra-warp ordering makes it safe).

namespace {
constexpr int B_  = 512;
constexpr int S_  = 480;
constexpr int F_  = 149;
constexpr int VF_ = 5;
constexpr int PAIR_ROWS = 32;             // rows per warp (two 16-row chains)
constexpr int PPB = S_ / PAIR_ROWS;       // 15 pairs per batch row
constexpr int WPB = 8;                    // 256 threads
constexpr int NBLK = B_ * PPB / WPB;      // 960
constexpr int STG_FLOATS = 600;           // 2400B >= delta(12) + 4*596B
constexpr int TV_FLOATS  = 84;            // 336B  >= delta(12) + 320B
}

__device__ double g_acc[3] = {0.0, 0.0, 0.0};
__device__ unsigned int g_ticket = 0;

// lane -> joint, part groups shuffle-aligned:
// lanes 0-7 part0, 8-11 part1, 12-15 part2, 16-19 part3, 20-23 part4
__constant__ int c_j[24] = {
    8, 9, 10, 11, 12, 21, 22, 23,
    0, 1, 2, 3,
    4, 5, 6, 7,
    13, 14, 15, 16,
    17, 18, 19, 20
};
__constant__ float c_wl[24] = {
    1.f/9, 1.f/9, 1.f/9, 1.f/9, 1.f/9, 1.f/9, 2.f/9, 1.f/9,
    0.1f, 0.2f, 0.3f, 0.4f,
    0.1f, 0.2f, 0.3f, 0.4f,
    0.1f, 0.2f, 0.3f, 0.4f,
    0.1f, 0.2f, 0.3f, 0.4f
};

__device__ __forceinline__ void cp16(unsigned sdst, const void* gsrc) {
    asm volatile("cp.async.cg.shared.global [%0], [%1], 16;" :: "r"(sdst), "l"(gsrc));
}
__device__ __forceinline__ void cp4(unsigned sdst, const void* gsrc) {
    asm volatile("cp.async.ca.shared.global [%0], [%1], 4;" :: "r"(sdst), "l"(gsrc));
}
__device__ __forceinline__ void commitg() { asm volatile("cp.async.commit_group;"); }
template <int N> __device__ __forceinline__ void waitg() {
    asm volatile("cp.async.wait_group %0;" :: "n"(N));
}

__global__ void __launch_bounds__(256, 4) vel_loss_dual(
    const float* __restrict__ pred,   // (B, S, F)
    const float* __restrict__ tvft,   // (B, S+1, VF)
    const float* __restrict__ meanv,  // (F,)
    const float* __restrict__ stdv,   // (F,)
    float* __restrict__ out)
{
    __shared__ __align__(16) float stg[WPB][2][STG_FLOATS];   // [warp][chain]
    __shared__ __align__(16) float tvs[WPB][2][TV_FLOATS];
    __shared__ double sA[WPB], sB[WPB], sC[WPB];

    const int tid  = threadIdx.x;
    const int lane = tid & 31;
    const int warp = tid >> 5;
    const int idx  = blockIdx.x * WPB + warp;     // pair id
    const int b    = idx / PPB;
    const int pr   = idx % PPB;
    const int s0A  = pr * PAIR_ROWS;
    const int s0B  = s0A + 16;
    const unsigned FULL = 0xffffffffu;

    const unsigned sbA = (unsigned)__cvta_generic_to_shared(&stg[warp][0][0]);
    const unsigned sbB = (unsigned)__cvta_generic_to_shared(&stg[warp][1][0]);
    const unsigned tvA = (unsigned)__cvta_generic_to_shared(&tvs[warp][0][0]);
    const unsigned tvB = (unsigned)__cvta_generic_to_shared(&tvs[warp][1][0]);

    // per-lane joint parameters
    int jj = 0; float w = 0.f;
    float sp0 = 0, sp1 = 0, sp2 = 0, rv0 = 0, rv1 = 0, rv2 = 0;
    float a0c = 0, a1c = 0, a2c = 0;
    const bool act = (lane < 24);
    if (act) {
        jj = c_j[lane] * 3;
        w  = c_wl[lane];
        sp0 = stdv[jj];     sp1 = stdv[jj + 1];     sp2 = stdv[jj + 2];
        rv0 = 1.0f / stdv[72 + jj];
        rv1 = 1.0f / stdv[72 + jj + 1];
        rv2 = 1.0f / stdv[72 + jj + 2];
        a0c = meanv[72 + jj]     * rv0;
        a1c = meanv[72 + jj + 1] * rv1;
        a2c = meanv[72 + jj + 2] * rv2;
    }
    int pidx = -1;
    if      (lane == 0)  pidx = 0;
    else if (lane == 8)  pidx = 1;
    else if (lane == 12) pidx = 2;
    else if (lane == 16) pidx = 3;
    else if (lane == 20) pidx = 4;
    float mfrf = 0.f, rf = 0.f;
    if (pidx >= 0) {
        rf = 1.0f / stdv[144 + pidx];
        mfrf = meanv[144 + pidx] * rf;
    }
    const int pid0 = (pidx >= 0) ? pidx : 0;

    float accA = 0.f, accB0 = 0.f, accC = 0.f;
    float pA0 = 0.f, pA1 = 0.f, pA2 = 0.f;
    float pB0 = 0.f, pB1 = 0.f, pB2 = 0.f;

    // ---- prologue LDGs (issued first; latency overlaps stage loads) ----
    const bool firstA = (s0A == 0);
    const int sBegA = firstA ? 1 : s0A;
    {
        const float* rA = pred + ((size_t)(b * S_ + s0A)) * F_;
        if (firstA) {
            if (act) {
                pA0 = rA[jj]; pA1 = rA[jj + 1]; pA2 = rA[jj + 2];
                const float q0 = rA[77 + jj], q1 = rA[78 + jj], q2 = rA[79 + jj];
                accB0 = q0 * q0 + q1 * q1 + q2 * q2;
            }
        } else if (act) {
            const float* rp = rA - F_;
            pA0 = rp[jj]; pA1 = rp[jj + 1]; pA2 = rp[jj + 2];
        }
        if (act) {
            const float* rpB = pred + ((size_t)(b * S_ + s0B - 1)) * F_;
            pB0 = rpB[jj]; pB1 = rpB[jj + 1]; pB2 = rpB[jj + 2];
        }
    }

    // ---- chain-invariant loader state ----
    const uintptr_t gbA = (uintptr_t)(pred + (size_t)(b * S_ + sBegA) * F_);
    const uintptr_t gbB = (uintptr_t)(pred + (size_t)(b * S_ + s0B) * F_);
    const char* gaA = (const char*)(gbA & ~(uintptr_t)15);
    const char* gaB = (const char*)(gbB & ~(uintptr_t)15);
    const int dbA = (int)(gbA & 15), dbB = (int)(gbB & 15);
    const int dfA = dbA >> 2,        dfB = dbB >> 2;
    const int nchA = (dbA + 4 * F_ * 4 + 15) >> 4;
    const int nchB = (dbB + 4 * F_ * 4 + 15) >> 4;
    const bool lastPair = (idx == B_ * PPB - 1);   // chain B stage3 = end of tensor

    auto loadStage = [&](const char* ga0, int nch, unsigned sdst, int t, bool useCp4) {
        const char* ga = ga0 + (size_t)t * (4 * F_ * 4);
        if (!useCp4) {
            #pragma unroll
            for (int i = 0; i < 5; ++i) {
                const int c = lane + i * 32;
                if (c < nch) cp16(sdst + c * 16, ga + c * 16);
            }
        } else {
            const int nw = (nch << 2) - 3;   // conservative word count from nch
            for (int i = lane; i < nw; i += 32)
                cp4(sdst + i * 4, ga + i * 4);
        }
        commitg();
    };

    // tv staging offsets
    const size_t ftvA = (size_t)(b * (S_ + 1) + sBegA) * VF_;
    const size_t ftvB = (size_t)(b * (S_ + 1) + s0B) * VF_;
    const uintptr_t gtA = (uintptr_t)(tvft + ftvA);
    const uintptr_t gtB = (uintptr_t)(tvft + ftvB);
    const int dtvA = (int)(ftvA & 3), dtvB = (int)(ftvB & 3);

    // ---- consume NR rows from a staged batch ----
    auto computeBatch = [&](const float* slab, int df, const float* tvp,
                            float& p0, float& p1, float& p2, auto nrc) {
        constexpr int NR = decltype(nrc)::value;
        const float* r0 = slab + df;
        float trv[NR];
        #pragma unroll
        for (int k = 0; k < NR; ++k) trv[k] = tvp[k * VF_];
        float contrib[NR];
        #pragma unroll
        for (int k = 0; k < NR; ++k) {
            contrib[k] = 0.f;
            if (act) {
                const float* rr = r0 + k * F_;
                const float c0 = rr[jj], c1 = rr[jj + 1], c2 = rr[jj + 2];
                const float q0 = rr[77 + jj], q1 = rr[78 + jj], q2 = rr[79 + jj];
                const float v0 = (c0 - p0) * sp0;
                const float v1 = (c1 - p1) * sp1;
                const float v2 = (c2 - p2) * sp2;
                const float d0 = q0 + a0c - v0 * rv0;
                const float d1 = q1 + a1c - v1 * rv1;
                const float d2 = q2 + a2c - v2 * rv2;
                accA += d0 * d0 + d1 * d1 + d2 * d2;
                contrib[k] = sqrtf(v0 * v0 + v1 * v1 + v2 * v2) * w;
                p0 = c0; p1 = c1; p2 = c2;
            }
        }
        float g4v[NR], g8v[NR];
        #pragma unroll
        for (int k = 0; k < NR; ++k) g4v[k] = contrib[k] + __shfl_xor_sync(FULL, contrib[k], 1);
        #pragma unroll
        for (int k = 0; k < NR; ++k) g4v[k] += __shfl_xor_sync(FULL, g4v[k], 2);
        #pragma unroll
        for (int k = 0; k < NR; ++k) g8v[k] = g4v[k] + __shfl_xor_sync(FULL, g4v[k], 4);
        if (pidx >= 0) {
            #pragma unroll
            for (int k = 0; k < NR; ++k) {
                const float f = (pidx == 0) ? g8v[k] : g4v[k];
                const float d = trv[k] + mfrf - f * rf;
                accC += d * d;
            }
        }
    };

    constexpr auto N4 = std::integral_constant<int, 4>{};
    constexpr auto N3 = std::integral_constant<int, 3>{};

    const float* slabA = &stg[warp][0][0];
    const float* slabB = &stg[warp][1][0];
    const float* tvpA0 = &tvs[warp][0][0] + dtvA + pid0;
    const float* tvpB0 = &tvs[warp][1][0] + dtvB + pid0;

    // ---- interleaved mainloop ----
    // g1: tvA + A0   g2: tvB + B0
    {
        const int nchTVA = ((int)(gtA & 15) + 16 * VF_ * 4 + 15) >> 4;
        if (lane < nchTVA) cp16(tvA + lane * 16, (const char*)(gtA & ~(uintptr_t)15) + lane * 16);
    }
    loadStage(gaA, nchA, sbA, 0, false);
    {
        const int nchTVB = ((int)(gtB & 15) + 16 * VF_ * 4 + 15) >> 4;
        if (lane < nchTVB) cp16(tvB + lane * 16, (const char*)(gtB & ~(uintptr_t)15) + lane * 16);
    }
    loadStage(gaB, nchB, sbB, 0, false);

    waitg<1>(); __syncwarp();
    computeBatch(slabA, dfA, tvpA0 + 0 * VF_, pA0, pA1, pA2, N4);
    loadStage(gaA, nchA, sbA, 1, false);
    waitg<1>(); __syncwarp();
    computeBatch(slabB, dfB, tvpB0 + 0 * VF_, pB0, pB1, pB2, N4);
    loadStage(gaB, nchB, sbB, 1, false);
    waitg<1>(); __syncwarp();
    computeBatch(slabA, dfA, tvpA0 + 4 * VF_, pA0, pA1, pA2, N4);
    loadStage(gaA, nchA, sbA, 2, false);
    waitg<1>(); __syncwarp();
    computeBatch(slabB, dfB, tvpB0 + 4 * VF_, pB0, pB1, pB2, N4);
    loadStage(gaB, nchB, sbB, 2, false);
    waitg<1>(); __syncwarp();
    computeBatch(slabA, dfA, tvpA0 + 8 * VF_, pA0, pA1, pA2, N4);
    loadStage(gaA, nchA, sbA, 3, false);
    waitg<1>(); __syncwarp();
    computeBatch(slabB, dfB, tvpB0 + 8 * VF_, pB0, pB1, pB2, N4);
    loadStage(gaB, nchB, sbB, 3, lastPair);
    waitg<1>(); __syncwarp();
    if (!firstA) computeBatch(slabA, dfA, tvpA0 + 12 * VF_, pA0, pA1, pA2, N4);
    else         computeBatch(slabA, dfA, tvpA0 + 12 * VF_, pA0, pA1, pA2, N3);
    waitg<0>(); __syncwarp();
    computeBatch(slabB, dfB, tvpB0 + 12 * VF_, pB0, pB1, pB2, N4);

    // ---- reductions ----
    #pragma unroll
    for (int off = 16; off; off >>= 1) {
        accA  += __shfl_xor_sync(FULL, accA, off);
        accB0 += __shfl_xor_sync(FULL, accB0, off);
        accC  += __shfl_xor_sync(FULL, accC, off);
    }
    if (lane == 0) {
        sA[warp] = (double)accA;
        sB[warp] = (double)accB0;
        sC[warp] = (double)accC;
    }
    __syncthreads();

    if (warp == 0) {
        double a  = (lane < WPB) ? sA[lane] : 0.0;
        double bb = (lane < WPB) ? sB[lane] : 0.0;
        double c  = (lane < WPB) ? sC[lane] : 0.0;
        #pragma unroll
        for (int off = 4; off; off >>= 1) {
            a  += __shfl_xor_sync(FULL, a, off);
            bb += __shfl_xor_sync(FULL, bb, off);
            c  += __shfl_xor_sync(FULL, c, off);
        }
        if (lane == 0) {
            atomicAdd(&g_acc[0], a);
            atomicAdd(&g_acc[1], bb);
            atomicAdd(&g_acc[2], c);
            __threadfence();
            const unsigned t = atomicAdd(&g_ticket, 1u);
            if (t == (unsigned)(NBLK - 1)) {
                __threadfence();
                volatile double* ga = g_acc;
                const double A  = ga[0];
                const double B0 = ga[1];
                const double C  = ga[2];
                const double nA  = (double)B_ * (double)(S_ - 1) * 72.0;
                const double nB2 = (double)B_ * 72.0;
                const double nC  = (double)B_ * (double)(S_ - 1) * (double)VF_;
                const double loss1 = 10.0 * A / nA + 20.0 * B0 / nB2;
                const double loss2 = 10.0 * C / nC;
                out[0] = (float)(2.0 * loss1 + 1.5 * loss2);
                ga[0] = 0.0; ga[1] = 0.0; ga[2] = 0.0;
                g_ticket = 0;
            }
        }
    }
}

extern "C" void kernel_launch(void* const* d_in, const int* in_sizes, int n_in,
                              void* d_out, int out_size) {
    const float* pred = (const float*)d_in[0];   // predict_seq (B,S,F)
    // d_in[1] = _train_x1 (unused), d_in[2] = _train_x2 (unused)
    const float* tvft = (const float*)d_in[3];   // _true_vel_factor (B,S+1,VF)
    const float* mean = (const float*)d_in[4];   // _mean (F,)
    const float* stdv = (const float*)d_in[5];   // _std (F,)

    vel_loss_dual<<<NBLK, 256>>>(pred, tvft, mean, stdv, (float*)d_out);
}